// round 12
// baseline (speedup 1.0000x reference)
#include <cuda_runtime.h>
#include <cuda_bf16.h>
#include <math.h>

// ---------------------------------------------------------------------------
// SINGLE-KERNEL fused pipeline (persistent grid + device grid barriers).
// 3x exact top-K over columns of A (N x 2), (value desc, index asc) = lax.top_k.
// 148 blocks x 512 threads; 4 grid barriers, ONE pass over A:
//   P1 hist    : 16384-bin histograms of fkey(v), fkey(vo); float4 kept in regs
//   P2 pick    : block 0 alone scans all bins (32/thread in regs, 512-wide
//                scan), writes g_base offset tables, thresholds, worklist
//   P3 compact : scatter candidates (values from REGISTERS) via atomicAdd
//   P4 rank    : one block per worklist entry (SUB=128 keys), rank-by-compare;
//                idle blocks zero g_hist for the next replay
//   P5 gemv    : 2 rows/warp gather + 512->2 GEMV (smem W) + softmax
// State zero at module load; each call re-zeroes => every call identical.
// Output (float32, 15K): [0,3K) labels | [3K,9K) logits | [9K,15K) softmax
// ---------------------------------------------------------------------------

#define NBINS   16384
#define SHIFT   18
#define PBPT    (NBINS / THR)      // 32 bins per thread in pick
#define SUB     128                // keys ranked per worklist entry
#define CAP     4096
#define KMAX    2048
#define SEGB    1024
#define WLCAP   8192
#define BLKS    148
#define THR     512

__device__ unsigned            g_hist[2][NBINS];
__device__ int                 g_base[3][NBINS];
__device__ unsigned            g_bin[3];            // lo0 (>=), hi1 (<=), lo2 (>=)
__device__ int                 g_nwork;
__device__ int4                g_work[WLCAP];       // {sel|sub<<2, bin, start, cnt}
__device__ unsigned long long  g_scat[3][CAP];
__device__ int                 g_idx[3 * KMAX];
__device__ unsigned            g_arrive;
__device__ volatile unsigned   g_gen;

__device__ __forceinline__ unsigned fkey(float f) {
    unsigned u = __float_as_uint(f);
    return (u & 0x80000000u) ? ~u : (u | 0x80000000u);   // monotonic
}

// Generation-counter grid barrier. Safe: 148 blocks, >=296 resident slots
// at __launch_bounds__(512, 2) on 152 SMs.
__device__ __forceinline__ void grid_sync() {
    __syncthreads();
    if (threadIdx.x == 0) {
        unsigned gen = g_gen;
        __threadfence();                               // release
        if (atomicAdd(&g_arrive, 1u) == (unsigned)BLKS - 1u) {
            g_arrive = 0u;
            __threadfence();
            g_gen = gen + 1u;
        } else {
            while (g_gen == gen) __nanosleep(32);
            __threadfence();                           // acquire
        }
    }
    __syncthreads();
}

__global__ __launch_bounds__(THR, 2)
void fused_kernel(const float* __restrict__ h, const float4* __restrict__ A4,
                  const float* __restrict__ W, const float* __restrict__ bvec,
                  const int* __restrict__ bag, float* __restrict__ out,
                  int N, int D, int K) {
    __shared__ unsigned long long s_u64[SEGB];        // 8KB, aliased per phase
    unsigned* s_u32 = (unsigned*)s_u64;
    float*    s_f   = (float*)s_u64;

    const int tid = threadIdx.x;
    const int bid = blockIdx.x;
    const int bg  = __ldg(bag);
    const unsigned uK = (unsigned)K;
    const int N2 = N >> 1;
    const int gsz = BLKS * THR;
    const int i0 = bid * THR + tid;

    // ---- P1: histograms; keep this thread's float4 in registers ---------------
    float4 areg = make_float4(0.f, 0.f, 0.f, 0.f);
    if (i0 < N2) areg = A4[i0];
    for (int i = i0; i < N2; i += gsz) {
        float4 a = (i == i0) ? areg : A4[i];
        float v0  = bg ? a.y : a.x,  vo0 = bg ? a.x : a.y;
        float v1  = bg ? a.w : a.z,  vo1 = bg ? a.z : a.w;
        atomicAdd(&g_hist[0][fkey(v0)  >> SHIFT], 1u);
        atomicAdd(&g_hist[1][fkey(vo0) >> SHIFT], 1u);
        atomicAdd(&g_hist[0][fkey(v1)  >> SHIFT], 1u);
        atomicAdd(&g_hist[1][fkey(vo1) >> SHIFT], 1u);
    }
    if ((N & 1) && bid == 0 && tid == 0) {
        const float2* A2 = (const float2*)A4;
        float2 a = A2[N - 1];
        float v = bg ? a.y : a.x, vo = bg ? a.x : a.y;
        atomicAdd(&g_hist[0][fkey(v)  >> SHIFT], 1u);
        atomicAdd(&g_hist[1][fkey(vo) >> SHIFT], 1u);
    }
    grid_sync();

    // ---- P2: single-block pick (block 0) ---------------------------------------
    if (bid == 0) {
        #pragma unroll
        for (int hh = 0; hh < 2; hh++) {
            const uint4* h4 = (const uint4*)g_hist[hh];
            unsigned cnt[PBPT];
            #pragma unroll
            for (int q = 0; q < PBPT / 4; q++) {
                uint4 c = h4[tid * (PBPT / 4) + q];
                cnt[q * 4 + 0] = c.x; cnt[q * 4 + 1] = c.y;
                cnt[q * 4 + 2] = c.z; cnt[q * 4 + 3] = c.w;
            }
            unsigned part = 0;
            #pragma unroll
            for (int j = 0; j < PBPT; j++) part += cnt[j];
            s_u32[tid] = part;
            __syncthreads();
            for (int off = 1; off < THR; off <<= 1) {     // inclusive scan
                unsigned w = (tid >= off) ? s_u32[tid - off] : 0u;
                __syncthreads();
                s_u32[tid] += w;
                __syncthreads();
            }
            const unsigned asc   = s_u32[tid];
            const unsigned total = s_u32[THR - 1];
            __syncthreads();

            int basev[PBPT];
            // top-K (sel0 from hist0, sel2 from hist1): suffix walk
            {
                const int selt = hh ? 2 : 0;
                unsigned acc = total - asc;
                #pragma unroll
                for (int j = PBPT - 1; j >= 0; j--) {
                    const int b = tid * PBPT + j;
                    basev[j] = (int)acc;
                    if (acc < uK && cnt[j] > 0) {
                        if (acc + cnt[j] >= uK) g_bin[selt] = (unsigned)b;
                        for (int sub = 0; sub * SUB < (int)cnt[j]; sub++) {
                            int w = atomicAdd(&g_nwork, 1);
                            if (w < WLCAP)
                                g_work[w] = make_int4(selt | (sub << 2), b,
                                                      (int)acc, (int)cnt[j]);
                        }
                    }
                    acc += cnt[j];
                }
                int4* gb4 = (int4*)g_base[selt];
                #pragma unroll
                for (int q = 0; q < PBPT / 4; q++)
                    gb4[tid * (PBPT / 4) + q] =
                        make_int4(basev[q * 4 + 0], basev[q * 4 + 1],
                                  basev[q * 4 + 2], basev[q * 4 + 3]);
            }
            // bottom-K (hist0 -> sel1): prefix walk
            if (hh == 0) {
                unsigned acc = asc - part;
                #pragma unroll
                for (int j = 0; j < PBPT; j++) {
                    const int b = tid * PBPT + j;
                    basev[j] = (int)acc;
                    if (acc < uK && cnt[j] > 0) {
                        if (acc + cnt[j] >= uK) g_bin[1] = (unsigned)b;
                        for (int sub = 0; sub * SUB < (int)cnt[j]; sub++) {
                            int w = atomicAdd(&g_nwork, 1);
                            if (w < WLCAP)
                                g_work[w] = make_int4(1 | (sub << 2), b,
                                                      (int)acc, (int)cnt[j]);
                        }
                    }
                    acc += cnt[j];
                }
                int4* gb4 = (int4*)g_base[1];
                #pragma unroll
                for (int q = 0; q < PBPT / 4; q++)
                    gb4[tid * (PBPT / 4) + q] =
                        make_int4(basev[q * 4 + 0], basev[q * 4 + 1],
                                  basev[q * 4 + 2], basev[q * 4 + 3]);
            }
            __syncthreads();
        }
    }
    grid_sync();

    // ---- P3: compact/scatter from REGISTERS ------------------------------------
    {
        const unsigned lo0 = g_bin[0], hi1 = g_bin[1], lo2 = g_bin[2];
        for (int i = i0; i < N2; i += gsz) {
            float4 a = (i == i0) ? areg : A4[i];
            #pragma unroll
            for (int e = 0; e < 2; e++) {
                float v  = e ? (bg ? a.w : a.z) : (bg ? a.y : a.x);
                float vo = e ? (bg ? a.z : a.w) : (bg ? a.x : a.y);
                const int idx = i * 2 + e;
                unsigned k0 = fkey(v), k2 = fkey(vo);
                unsigned b0 = k0 >> SHIFT, b2 = k2 >> SHIFT;
                unsigned long long il = (unsigned)(~(unsigned)idx);
                if (b0 >= lo0) {
                    int p = atomicAdd(&g_base[0][b0], 1);
                    if (p < CAP) g_scat[0][p] = ((unsigned long long)k0 << 32) | il;
                }
                if (b0 <= hi1) {
                    int p = atomicAdd(&g_base[1][b0], 1);
                    if (p < CAP) g_scat[1][p] = ((unsigned long long)(~k0) << 32) | il;
                }
                if (b2 >= lo2) {
                    int p = atomicAdd(&g_base[2][b2], 1);
                    if (p < CAP) g_scat[2][p] = ((unsigned long long)k2 << 32) | il;
                }
            }
        }
        if ((N & 1) && bid == 0 && tid == 0) {
            const float2* A2 = (const float2*)A4;
            float2 a = A2[N - 1];
            float v = bg ? a.y : a.x, vo = bg ? a.x : a.y;
            unsigned k0 = fkey(v), k2 = fkey(vo);
            unsigned b0 = k0 >> SHIFT, b2 = k2 >> SHIFT;
            unsigned long long il = (unsigned)(~(unsigned)(N - 1));
            if (b0 >= lo0) {
                int p = atomicAdd(&g_base[0][b0], 1);
                if (p < CAP) g_scat[0][p] = ((unsigned long long)k0 << 32) | il;
            }
            if (b0 <= hi1) {
                int p = atomicAdd(&g_base[1][b0], 1);
                if (p < CAP) g_scat[1][p] = ((unsigned long long)(~k0) << 32) | il;
            }
            if (b2 >= lo2) {
                int p = atomicAdd(&g_base[2][b2], 1);
                if (p < CAP) g_scat[2][p] = ((unsigned long long)k2 << 32) | il;
            }
        }
    }
    grid_sync();

    // ---- P4: rank worklist entries; then zero g_hist (hist is dead now) --------
    {
        const int nwork = g_nwork < WLCAP ? g_nwork : WLCAP;
        for (int e = bid; e < nwork; e += BLKS) {
            int4 w = g_work[e];
            const int sel = w.x & 3, sub = w.x >> 2;
            const int start = w.z;
            int cnt = w.w;
            if (start + cnt > CAP) cnt = CAP - start;
            if (cnt > SEGB) cnt = SEGB;
            const int lo = sub * SUB;
            int hi = lo + SUB; if (hi > cnt) hi = cnt;
            if (lo >= cnt) continue;
            const unsigned long long* seg = &g_scat[sel][start];

            if (cnt == 1) {
                if (tid == 0 && start < K)
                    g_idx[sel * K + start] = (int)(~(unsigned)(seg[0] & 0xFFFFFFFFull));
                continue;
            }
            for (int j = tid; j < cnt; j += THR) s_u64[j] = seg[j];
            __syncthreads();
            for (int i = lo + tid; i < hi; i += THR) {
                unsigned long long key = s_u64[i];
                int rank = 0;
                int j = 0;
                #pragma unroll 4
                for (; j + 3 < cnt; j += 4) {
                    rank += (s_u64[j]     > key);
                    rank += (s_u64[j + 1] > key);
                    rank += (s_u64[j + 2] > key);
                    rank += (s_u64[j + 3] > key);
                }
                for (; j < cnt; j++) rank += (s_u64[j] > key);
                int pos = start + rank;
                if (pos < K)
                    g_idx[sel * K + pos] = (int)(~(unsigned)(key & 0xFFFFFFFFull));
            }
            __syncthreads();
        }
        // zero g_hist for the next graph replay (unused after P2)
        uint4* hp = (uint4*)g_hist;
        const int totalw = 2 * NBINS / 4;
        for (int i = bid * THR + tid; i < totalw; i += gsz)
            hp[i] = make_uint4(0u, 0u, 0u, 0u);
    }
    grid_sync();

    // ---- P5: gemv/softmax (2 rows per warp); reset g_nwork ----------------------
    {
        if (bid == 0 && tid == 0) g_nwork = 0;

        float* ws0 = s_f;            // [0,D): W[:,0]
        float* ws1 = s_f + D;        // [D,2D): W[:,1]
        for (int j = tid; j < D; j += THR) {
            ws0[j] = W[j * 2 + 0];
            ws1[j] = W[j * 2 + 1];
        }
        __syncthreads();
        const float4* w04 = (const float4*)ws0;
        const float4* w14 = (const float4*)ws1;

        const int warp = tid >> 5, lane = tid & 31;
        const int nwarps = BLKS * (THR >> 5);
        const int wgid = bid * (THR >> 5) + warp;
        const int total = 3 * K;
        const int nq = D >> 2;
        const float bb0 = bvec[0], bb1 = bvec[1];

        for (int rbase = wgid * 2; rbase < total; rbase += nwarps * 2) {
            const bool two = (rbase + 1 < total);
            const int ia = g_idx[rbase];
            const int ib = two ? g_idx[rbase + 1] : ia;
            const float4* pa = (const float4*)(h + (size_t)ia * D);
            const float4* pb = (const float4*)(h + (size_t)ib * D);

            float a0 = 0.f, a1 = 0.f, b0 = 0.f, b1 = 0.f;
            int t = lane;
            for (; t + 96 < nq; t += 128) {
                float4 va0 = pa[t];
                float4 va1 = pa[t + 32];
                float4 va2 = pa[t + 64];
                float4 va3 = pa[t + 96];
                float4 vb0 = pb[t];
                float4 vb1 = pb[t + 32];
                float4 vb2 = pb[t + 64];
                float4 vb3 = pb[t + 96];
                #pragma unroll
                for (int u = 0; u < 4; u++) {
                    float4 va = (u == 0) ? va0 : (u == 1) ? va1 : (u == 2) ? va2 : va3;
                    float4 vb = (u == 0) ? vb0 : (u == 1) ? vb1 : (u == 2) ? vb2 : vb3;
                    float4 w0 = w04[t + u * 32];
                    float4 w1 = w14[t + u * 32];
                    a0 = fmaf(va.x, w0.x, a0);  a1 = fmaf(va.x, w1.x, a1);
                    b0 = fmaf(vb.x, w0.x, b0);  b1 = fmaf(vb.x, w1.x, b1);
                    a0 = fmaf(va.y, w0.y, a0);  a1 = fmaf(va.y, w1.y, a1);
                    b0 = fmaf(vb.y, w0.y, b0);  b1 = fmaf(vb.y, w1.y, b1);
                    a0 = fmaf(va.z, w0.z, a0);  a1 = fmaf(va.z, w1.z, a1);
                    b0 = fmaf(vb.z, w0.z, b0);  b1 = fmaf(vb.z, w1.z, b1);
                    a0 = fmaf(va.w, w0.w, a0);  a1 = fmaf(va.w, w1.w, a1);
                    b0 = fmaf(vb.w, w0.w, b0);  b1 = fmaf(vb.w, w1.w, b1);
                }
            }
            for (; t < nq; t += 32) {
                float4 va = pa[t];
                float4 vb = pb[t];
                float4 w0 = w04[t];
                float4 w1 = w14[t];
                a0 = fmaf(va.x, w0.x, a0);  a1 = fmaf(va.x, w1.x, a1);
                b0 = fmaf(vb.x, w0.x, b0);  b1 = fmaf(vb.x, w1.x, b1);
                a0 = fmaf(va.y, w0.y, a0);  a1 = fmaf(va.y, w1.y, a1);
                b0 = fmaf(vb.y, w0.y, b0);  b1 = fmaf(vb.y, w1.y, b1);
                a0 = fmaf(va.z, w0.z, a0);  a1 = fmaf(va.z, w1.z, a1);
                b0 = fmaf(vb.z, w0.z, b0);  b1 = fmaf(vb.z, w1.z, b1);
                a0 = fmaf(va.w, w0.w, a0);  a1 = fmaf(va.w, w1.w, a1);
                b0 = fmaf(vb.w, w0.w, b0);  b1 = fmaf(vb.w, w1.w, b1);
            }
            #pragma unroll
            for (int o = 16; o; o >>= 1) {
                a0 += __shfl_down_sync(0xFFFFFFFFu, a0, o);
                a1 += __shfl_down_sync(0xFFFFFFFFu, a1, o);
                b0 += __shfl_down_sync(0xFFFFFFFFu, b0, o);
                b1 += __shfl_down_sync(0xFFFFFFFFu, b1, o);
            }
            if (lane == 0) {
                {
                    int r = rbase;
                    float z0 = a0 + bb0, z1 = a1 + bb1;
                    float m = fmaxf(z0, z1);
                    float e0 = expf(z0 - m), e1 = expf(z1 - m);
                    float inv = 1.0f / (e0 + e1);
                    out[r] = (r < K) ? 1.0f : 0.0f;
                    out[3 * K + r * 2 + 0] = z0;
                    out[3 * K + r * 2 + 1] = z1;
                    out[9 * K + r * 2 + 0] = e0 * inv;
                    out[9 * K + r * 2 + 1] = e1 * inv;
                }
                if (two) {
                    int r = rbase + 1;
                    float z0 = b0 + bb0, z1 = b1 + bb1;
                    float m = fmaxf(z0, z1);
                    float e0 = expf(z0 - m), e1 = expf(z1 - m);
                    float inv = 1.0f / (e0 + e1);
                    out[r] = (r < K) ? 1.0f : 0.0f;
                    out[3 * K + r * 2 + 0] = z0;
                    out[3 * K + r * 2 + 1] = z1;
                    out[9 * K + r * 2 + 0] = e0 * inv;
                    out[9 * K + r * 2 + 1] = e1 * inv;
                }
            }
        }
    }
}

extern "C" void kernel_launch(void* const* d_in, const int* in_sizes, int n_in,
                              void* d_out, int out_size) {
    const float* h = (const float*)d_in[0];   // (N,1,D)
    const float* A = (const float*)d_in[1];   // (N,1,2)
    const float* W = (const float*)d_in[2];   // (D,2)
    const float* b = (const float*)d_in[3];   // (2,)
    const int* bag = (const int*)d_in[4];

    const int N = in_sizes[1] / 2;
    const int D = in_sizes[0] / N;
    int K = (int)(0.02 * (double)N);
    if (K == 0) K = 8;
    if (K > KMAX) K = KMAX;

    fused_kernel<<<BLKS, THR>>>(h, (const float4*)A, W, b, bag,
                                (float*)d_out, N, D, K);
}

// round 13
// speedup vs baseline: 1.1472x; 1.1472x over previous
#include <cuda_runtime.h>
#include <cuda_bf16.h>
#include <math.h>

// ---------------------------------------------------------------------------
// SINGLE-KERNEL fused pipeline (persistent grid + device grid barriers).
// 3x exact top-K over columns of A (N x 2), (value desc, index asc) = lax.top_k.
// 148 blocks x 512 threads; 4 grid barriers, ONE pass over A:
//   P1 hist    : 16384-bin histograms of fkey(v), fkey(vo) + fused per-chunk
//                sums (atomicAdd to 128 chunk counters); A float4 kept in regs
//   P2 base    : 128 blocks: each scans the 128 chunk sums (smem) + its own
//                128 bins; writes g_base, thresholds, worklist (SUB-split)
//   P3 compact : scatter candidates (values from REGISTERS) via atomicAdd
//   P4 rank    : one block per worklist entry, rank-by-comparison; idle
//                threads zero g_hist/g_bsum for the next replay
//   P5 gemv    : 2 rows/warp gather + 512->2 GEMV (smem W) + softmax
// State zero at module load; each call re-zeroes => every call identical.
// Output (float32, 15K): [0,3K) labels | [3K,9K) logits | [9K,15K) softmax
// ---------------------------------------------------------------------------

#define NBINS   16384
#define SHIFT   18
#define NCHUNK  128
#define CH      128                // bins per chunk
#define SUB     128                // keys ranked per worklist entry
#define CAP     4096
#define KMAX    2048
#define SEGB    1024
#define WLCAP   8192
#define BLKS    148
#define THR     512

__device__ unsigned            g_hist[2][NBINS];
__device__ unsigned            g_bsum[2][NCHUNK];
__device__ int                 g_base[3][NBINS];
__device__ unsigned            g_bin[3];            // lo0 (>=), hi1 (<=), lo2 (>=)
__device__ int                 g_nwork;
__device__ int4                g_work[WLCAP];       // {sel|sub<<2, bin, start, cnt}
__device__ unsigned long long  g_scat[3][CAP];
__device__ int                 g_idx[3 * KMAX];
__device__ unsigned            g_arrive;
__device__ volatile unsigned   g_gen;

__device__ __forceinline__ unsigned fkey(float f) {
    unsigned u = __float_as_uint(f);
    return (u & 0x80000000u) ? ~u : (u | 0x80000000u);   // monotonic
}

// Generation-counter grid barrier. Safe: 148 blocks, >=296 resident slots
// at __launch_bounds__(512, 2) on 152 SMs.
__device__ __forceinline__ void grid_sync() {
    __syncthreads();
    if (threadIdx.x == 0) {
        unsigned gen = g_gen;
        __threadfence();                               // release
        if (atomicAdd(&g_arrive, 1u) == (unsigned)BLKS - 1u) {
            g_arrive = 0u;
            __threadfence();
            g_gen = gen + 1u;
        } else {
            while (g_gen == gen) __nanosleep(32);
            __threadfence();                           // acquire
        }
    }
    __syncthreads();
}

__device__ __forceinline__ void hist_add(unsigned k, int hh) {
    unsigned bin = k >> SHIFT;
    atomicAdd(&g_hist[hh][bin], 1u);
    atomicAdd(&g_bsum[hh][bin >> 7], 1u);
}

__global__ __launch_bounds__(THR, 2)
void fused_kernel(const float* __restrict__ h, const float4* __restrict__ A4,
                  const float* __restrict__ W, const float* __restrict__ bvec,
                  const int* __restrict__ bag, float* __restrict__ out,
                  int N, int D, int K) {
    __shared__ unsigned long long s_u64[SEGB];        // 8KB, aliased per phase
    unsigned* s_u32 = (unsigned*)s_u64;
    float*    s_f   = (float*)s_u64;

    const int tid = threadIdx.x;
    const int bid = blockIdx.x;
    const int bg  = __ldg(bag);
    const unsigned uK = (unsigned)K;
    const int N2 = N >> 1;
    const int gsz = BLKS * THR;
    const int i0 = bid * THR + tid;

    // ---- P1: histograms + fused chunk sums; keep this thread's float4 ---------
    float4 areg = make_float4(0.f, 0.f, 0.f, 0.f);
    if (i0 < N2) areg = A4[i0];
    for (int i = i0; i < N2; i += gsz) {
        float4 a = (i == i0) ? areg : A4[i];
        float v0  = bg ? a.y : a.x,  vo0 = bg ? a.x : a.y;
        float v1  = bg ? a.w : a.z,  vo1 = bg ? a.z : a.w;
        hist_add(fkey(v0),  0);
        hist_add(fkey(vo0), 1);
        hist_add(fkey(v1),  0);
        hist_add(fkey(vo1), 1);
    }
    if ((N & 1) && bid == 0 && tid == 0) {
        const float2* A2 = (const float2*)A4;
        float2 a = A2[N - 1];
        hist_add(fkey(bg ? a.y : a.x), 0);
        hist_add(fkey(bg ? a.x : a.y), 1);
    }
    grid_sync();

    // ---- P2: offset tables + thresholds + worklist (blocks < NCHUNK) ----------
    if (bid < NCHUNK) {
        #pragma unroll
        for (int hh = 0; hh < 2; hh++) {
            // scan the NCHUNK chunk sums (every block redundantly)
            if (tid < NCHUNK) s_u32[tid] = g_bsum[hh][tid];
            __syncthreads();
            for (int off = 1; off < NCHUNK; off <<= 1) {
                unsigned w = (tid < NCHUNK && tid >= off) ? s_u32[tid - off] : 0u;
                __syncthreads();
                if (tid < NCHUNK) s_u32[tid] += w;
                __syncthreads();
            }
            const unsigned total = s_u32[NCHUNK - 1];
            const unsigned choff = s_u32[bid] - g_bsum[hh][bid];
            __syncthreads();

            // scan my chunk's CH bins
            unsigned cnt = 0;
            if (tid < CH) { cnt = g_hist[hh][bid * CH + tid]; s_u32[tid] = cnt; }
            __syncthreads();
            for (int off = 1; off < CH; off <<= 1) {
                unsigned w = (tid < CH && tid >= off) ? s_u32[tid - off] : 0u;
                __syncthreads();
                if (tid < CH) s_u32[tid] += w;
                __syncthreads();
            }
            if (tid < CH) {
                const int b = bid * CH + tid;
                const unsigned incl = s_u32[tid] + choff;
                // top-K (sel0 from hist0, sel2 from hist1)
                const int selt = hh ? 2 : 0;
                const unsigned above = total - incl;
                g_base[selt][b] = (int)above;
                if (above < uK && cnt > 0) {
                    if (above + cnt >= uK) g_bin[selt] = (unsigned)b;
                    for (int sub = 0; sub * SUB < (int)cnt; sub++) {
                        int w = atomicAdd(&g_nwork, 1);
                        if (w < WLCAP)
                            g_work[w] = make_int4(selt | (sub << 2), b, (int)above, (int)cnt);
                    }
                }
                // bottom-K (hist0 -> sel1)
                if (hh == 0) {
                    const unsigned below = incl - cnt;
                    g_base[1][b] = (int)below;
                    if (below < uK && cnt > 0) {
                        if (below + cnt >= uK) g_bin[1] = (unsigned)b;
                        for (int sub = 0; sub * SUB < (int)cnt; sub++) {
                            int w = atomicAdd(&g_nwork, 1);
                            if (w < WLCAP)
                                g_work[w] = make_int4(1 | (sub << 2), b, (int)below, (int)cnt);
                        }
                    }
                }
            }
            __syncthreads();
        }
    }
    grid_sync();

    // ---- P3: compact/scatter from REGISTERS ------------------------------------
    {
        const unsigned lo0 = g_bin[0], hi1 = g_bin[1], lo2 = g_bin[2];
        for (int i = i0; i < N2; i += gsz) {
            float4 a = (i == i0) ? areg : A4[i];
            #pragma unroll
            for (int e = 0; e < 2; e++) {
                float v  = e ? (bg ? a.w : a.z) : (bg ? a.y : a.x);
                float vo = e ? (bg ? a.z : a.w) : (bg ? a.x : a.y);
                const int idx = i * 2 + e;
                unsigned k0 = fkey(v), k2 = fkey(vo);
                unsigned b0 = k0 >> SHIFT, b2 = k2 >> SHIFT;
                unsigned long long il = (unsigned)(~(unsigned)idx);
                if (b0 >= lo0) {
                    int p = atomicAdd(&g_base[0][b0], 1);
                    if (p < CAP) g_scat[0][p] = ((unsigned long long)k0 << 32) | il;
                }
                if (b0 <= hi1) {
                    int p = atomicAdd(&g_base[1][b0], 1);
                    if (p < CAP) g_scat[1][p] = ((unsigned long long)(~k0) << 32) | il;
                }
                if (b2 >= lo2) {
                    int p = atomicAdd(&g_base[2][b2], 1);
                    if (p < CAP) g_scat[2][p] = ((unsigned long long)k2 << 32) | il;
                }
            }
        }
        if ((N & 1) && bid == 0 && tid == 0) {
            const float2* A2 = (const float2*)A4;
            float2 a = A2[N - 1];
            float v = bg ? a.y : a.x, vo = bg ? a.x : a.y;
            unsigned k0 = fkey(v), k2 = fkey(vo);
            unsigned b0 = k0 >> SHIFT, b2 = k2 >> SHIFT;
            unsigned long long il = (unsigned)(~(unsigned)(N - 1));
            if (b0 >= lo0) {
                int p = atomicAdd(&g_base[0][b0], 1);
                if (p < CAP) g_scat[0][p] = ((unsigned long long)k0 << 32) | il;
            }
            if (b0 <= hi1) {
                int p = atomicAdd(&g_base[1][b0], 1);
                if (p < CAP) g_scat[1][p] = ((unsigned long long)(~k0) << 32) | il;
            }
            if (b2 >= lo2) {
                int p = atomicAdd(&g_base[2][b2], 1);
                if (p < CAP) g_scat[2][p] = ((unsigned long long)k2 << 32) | il;
            }
        }
    }
    grid_sync();

    // ---- P4: rank worklist entries; zero g_hist/g_bsum (dead after P2) ---------
    {
        const int nwork = g_nwork < WLCAP ? g_nwork : WLCAP;
        for (int e = bid; e < nwork; e += BLKS) {
            int4 w = g_work[e];
            const int sel = w.x & 3, sub = w.x >> 2;
            const int start = w.z;
            int cnt = w.w;
            if (start + cnt > CAP) cnt = CAP - start;
            if (cnt > SEGB) cnt = SEGB;
            const int lo = sub * SUB;
            int hi = lo + SUB; if (hi > cnt) hi = cnt;
            if (lo >= cnt) continue;
            const unsigned long long* seg = &g_scat[sel][start];

            if (cnt == 1) {
                if (tid == 0 && start < K)
                    g_idx[sel * K + start] = (int)(~(unsigned)(seg[0] & 0xFFFFFFFFull));
                continue;
            }
            for (int j = tid; j < cnt; j += THR) s_u64[j] = seg[j];
            __syncthreads();
            for (int i = lo + tid; i < hi; i += THR) {
                unsigned long long key = s_u64[i];
                int rank = 0;
                int j = 0;
                #pragma unroll 4
                for (; j + 3 < cnt; j += 4) {
                    rank += (s_u64[j]     > key);
                    rank += (s_u64[j + 1] > key);
                    rank += (s_u64[j + 2] > key);
                    rank += (s_u64[j + 3] > key);
                }
                for (; j < cnt; j++) rank += (s_u64[j] > key);
                int pos = start + rank;
                if (pos < K)
                    g_idx[sel * K + pos] = (int)(~(unsigned)(key & 0xFFFFFFFFull));
            }
            __syncthreads();
        }
        // zero histograms + chunk sums for the next graph replay
        uint4* hp = (uint4*)g_hist;
        const int totalw = 2 * NBINS / 4;
        for (int i = bid * THR + tid; i < totalw; i += gsz)
            hp[i] = make_uint4(0u, 0u, 0u, 0u);
        if (bid == BLKS - 1 && tid < 2 * NCHUNK)
            ((unsigned*)g_bsum)[tid] = 0u;
    }
    grid_sync();

    // ---- P5: gemv/softmax (2 rows per warp); reset g_nwork ----------------------
    {
        if (bid == 0 && tid == 0) g_nwork = 0;

        float* ws0 = s_f;            // [0,D): W[:,0]
        float* ws1 = s_f + D;        // [D,2D): W[:,1]
        for (int j = tid; j < D; j += THR) {
            ws0[j] = W[j * 2 + 0];
            ws1[j] = W[j * 2 + 1];
        }
        __syncthreads();
        const float4* w04 = (const float4*)ws0;
        const float4* w14 = (const float4*)ws1;

        const int warp = tid >> 5, lane = tid & 31;
        const int nwarps = BLKS * (THR >> 5);
        const int wgid = bid * (THR >> 5) + warp;
        const int total = 3 * K;
        const int nq = D >> 2;
        const float bb0 = bvec[0], bb1 = bvec[1];

        for (int rbase = wgid * 2; rbase < total; rbase += nwarps * 2) {
            const bool two = (rbase + 1 < total);
            const int ia = g_idx[rbase];
            const int ib = two ? g_idx[rbase + 1] : ia;
            const float4* pa = (const float4*)(h + (size_t)ia * D);
            const float4* pb = (const float4*)(h + (size_t)ib * D);

            float a0 = 0.f, a1 = 0.f, b0 = 0.f, b1 = 0.f;
            int t = lane;
            for (; t + 96 < nq; t += 128) {
                float4 va0 = pa[t];
                float4 va1 = pa[t + 32];
                float4 va2 = pa[t + 64];
                float4 va3 = pa[t + 96];
                float4 vb0 = pb[t];
                float4 vb1 = pb[t + 32];
                float4 vb2 = pb[t + 64];
                float4 vb3 = pb[t + 96];
                #pragma unroll
                for (int u = 0; u < 4; u++) {
                    float4 va = (u == 0) ? va0 : (u == 1) ? va1 : (u == 2) ? va2 : va3;
                    float4 vb = (u == 0) ? vb0 : (u == 1) ? vb1 : (u == 2) ? vb2 : vb3;
                    float4 w0 = w04[t + u * 32];
                    float4 w1 = w14[t + u * 32];
                    a0 = fmaf(va.x, w0.x, a0);  a1 = fmaf(va.x, w1.x, a1);
                    b0 = fmaf(vb.x, w0.x, b0);  b1 = fmaf(vb.x, w1.x, b1);
                    a0 = fmaf(va.y, w0.y, a0);  a1 = fmaf(va.y, w1.y, a1);
                    b0 = fmaf(vb.y, w0.y, b0);  b1 = fmaf(vb.y, w1.y, b1);
                    a0 = fmaf(va.z, w0.z, a0);  a1 = fmaf(va.z, w1.z, a1);
                    b0 = fmaf(vb.z, w0.z, b0);  b1 = fmaf(vb.z, w1.z, b1);
                    a0 = fmaf(va.w, w0.w, a0);  a1 = fmaf(va.w, w1.w, a1);
                    b0 = fmaf(vb.w, w0.w, b0);  b1 = fmaf(vb.w, w1.w, b1);
                }
            }
            for (; t < nq; t += 32) {
                float4 va = pa[t];
                float4 vb = pb[t];
                float4 w0 = w04[t];
                float4 w1 = w14[t];
                a0 = fmaf(va.x, w0.x, a0);  a1 = fmaf(va.x, w1.x, a1);
                b0 = fmaf(vb.x, w0.x, b0);  b1 = fmaf(vb.x, w1.x, b1);
                a0 = fmaf(va.y, w0.y, a0);  a1 = fmaf(va.y, w1.y, a1);
                b0 = fmaf(vb.y, w0.y, b0);  b1 = fmaf(vb.y, w1.y, b1);
                a0 = fmaf(va.z, w0.z, a0);  a1 = fmaf(va.z, w1.z, a1);
                b0 = fmaf(vb.z, w0.z, b0);  b1 = fmaf(vb.z, w1.z, b1);
                a0 = fmaf(va.w, w0.w, a0);  a1 = fmaf(va.w, w1.w, a1);
                b0 = fmaf(vb.w, w0.w, b0);  b1 = fmaf(vb.w, w1.w, b1);
            }
            #pragma unroll
            for (int o = 16; o; o >>= 1) {
                a0 += __shfl_down_sync(0xFFFFFFFFu, a0, o);
                a1 += __shfl_down_sync(0xFFFFFFFFu, a1, o);
                b0 += __shfl_down_sync(0xFFFFFFFFu, b0, o);
                b1 += __shfl_down_sync(0xFFFFFFFFu, b1, o);
            }
            if (lane == 0) {
                {
                    int r = rbase;
                    float z0 = a0 + bb0, z1 = a1 + bb1;
                    float m = fmaxf(z0, z1);
                    float e0 = expf(z0 - m), e1 = expf(z1 - m);
                    float inv = 1.0f / (e0 + e1);
                    out[r] = (r < K) ? 1.0f : 0.0f;
                    out[3 * K + r * 2 + 0] = z0;
                    out[3 * K + r * 2 + 1] = z1;
                    out[9 * K + r * 2 + 0] = e0 * inv;
                    out[9 * K + r * 2 + 1] = e1 * inv;
                }
                if (two) {
                    int r = rbase + 1;
                    float z0 = b0 + bb0, z1 = b1 + bb1;
                    float m = fmaxf(z0, z1);
                    float e0 = expf(z0 - m), e1 = expf(z1 - m);
                    float inv = 1.0f / (e0 + e1);
                    out[r] = (r < K) ? 1.0f : 0.0f;
                    out[3 * K + r * 2 + 0] = z0;
                    out[3 * K + r * 2 + 1] = z1;
                    out[9 * K + r * 2 + 0] = e0 * inv;
                    out[9 * K + r * 2 + 1] = e1 * inv;
                }
            }
        }
    }
}

extern "C" void kernel_launch(void* const* d_in, const int* in_sizes, int n_in,
                              void* d_out, int out_size) {
    const float* h = (const float*)d_in[0];   // (N,1,D)
    const float* A = (const float*)d_in[1];   // (N,1,2)
    const float* W = (const float*)d_in[2];   // (D,2)
    const float* b = (const float*)d_in[3];   // (2,)
    const int* bag = (const int*)d_in[4];

    const int N = in_sizes[1] / 2;
    const int D = in_sizes[0] / N;
    int K = (int)(0.02 * (double)N);
    if (K == 0) K = 8;
    if (K > KMAX) K = KMAX;

    fused_kernel<<<BLKS, THR>>>(h, (const float4*)A, W, b, bag,
                                (float*)d_out, N, D, K);
}

// round 15
// speedup vs baseline: 2.2156x; 1.9313x over previous
#include <cuda_runtime.h>
#include <cuda_bf16.h>
#include <math.h>

// ---------------------------------------------------------------------------
// SINGLE-KERNEL fused pipeline (persistent grid + device grid barriers).
// 3x exact top-K over columns of A (N x 2), (value desc, index asc) = lax.top_k.
// 148 blocks x 512 threads; 4 grid barriers, ONE pass over A:
//   P1 hist    : 16384-bin global histograms of fkey(v), fkey(vo);
//                A float4 kept in registers for reuse in P3
//   P2 base    : 128 blocks; each block recomputes the 128 chunk sums from
//                g_hist (scalar sums, smem reduce+scan — no register arrays),
//                then scans its own 128 bins; writes g_base, thresholds,
//                worklist (fat bins SUB-split)
//   P3 compact : scatter candidates (A values from REGISTERS) via atomicAdd
//   P4 rank    : one block per worklist entry, rank-by-comparison; also zeroes
//                g_hist for the next replay
//   P5 gemv    : 2 rows/warp gather + 512->2 GEMV (smem W) + softmax
// State zero at module load; each call re-zeroes => every call identical.
// Output (float32, 15K): [0,3K) labels | [3K,9K) logits | [9K,15K) softmax
// ---------------------------------------------------------------------------

#define NBINS   16384
#define SHIFT   18
#define NCHUNK  128
#define CH      128                // bins per chunk
#define BPT     32                 // bins summed per thread in P2 (512*32=16384)
#define SUB     128                // keys ranked per worklist entry
#define CAP     4096
#define KMAX    2048
#define SEGB    1024
#define WLCAP   8192
#define BLKS    148
#define THR     512

__device__ unsigned            g_hist[2][NBINS];
__device__ int                 g_base[3][NBINS];
__device__ unsigned            g_bin[3];            // lo0 (>=), hi1 (<=), lo2 (>=)
__device__ int                 g_nwork;
__device__ int4                g_work[WLCAP];       // {sel|sub<<2, bin, start, cnt}
__device__ unsigned long long  g_scat[3][CAP];
__device__ int                 g_idx[3 * KMAX];
__device__ unsigned            g_arrive;
__device__ volatile unsigned   g_gen;

__device__ __forceinline__ unsigned fkey(float f) {
    unsigned u = __float_as_uint(f);
    return (u & 0x80000000u) ? ~u : (u | 0x80000000u);   // monotonic
}

// Generation-counter grid barrier. Safe: 148 blocks, >=296 resident slots
// at __launch_bounds__(512, 2) on 152 SMs.
__device__ __forceinline__ void grid_sync() {
    __syncthreads();
    if (threadIdx.x == 0) {
        unsigned gen = g_gen;
        __threadfence();                               // release
        if (atomicAdd(&g_arrive, 1u) == (unsigned)BLKS - 1u) {
            g_arrive = 0u;
            __threadfence();
            g_gen = gen + 1u;
        } else {
            while (g_gen == gen) __nanosleep(32);
            __threadfence();                           // acquire
        }
    }
    __syncthreads();
}

__global__ __launch_bounds__(THR, 2)
void fused_kernel(const float* __restrict__ h, const float4* __restrict__ A4,
                  const float* __restrict__ W, const float* __restrict__ bvec,
                  const int* __restrict__ bag, float* __restrict__ out,
                  int N, int D, int K) {
    __shared__ unsigned long long s_u64[SEGB];        // 8KB = 2048 u32, aliased
    unsigned* s_u32 = (unsigned*)s_u64;
    float*    s_f   = (float*)s_u64;

    const int tid = threadIdx.x;
    const int bid = blockIdx.x;
    const int bg  = __ldg(bag);
    const unsigned uK = (unsigned)K;
    const int N2 = N >> 1;
    const int gsz = BLKS * THR;
    const int i0 = bid * THR + tid;

    // ---- P1: histograms; keep this thread's float4 in registers ---------------
    float4 areg = make_float4(0.f, 0.f, 0.f, 0.f);
    if (i0 < N2) areg = A4[i0];
    for (int i = i0; i < N2; i += gsz) {
        float4 a = (i == i0) ? areg : A4[i];
        float v0  = bg ? a.y : a.x,  vo0 = bg ? a.x : a.y;
        float v1  = bg ? a.w : a.z,  vo1 = bg ? a.z : a.w;
        atomicAdd(&g_hist[0][fkey(v0)  >> SHIFT], 1u);
        atomicAdd(&g_hist[1][fkey(vo0) >> SHIFT], 1u);
        atomicAdd(&g_hist[0][fkey(v1)  >> SHIFT], 1u);
        atomicAdd(&g_hist[1][fkey(vo1) >> SHIFT], 1u);
    }
    if ((N & 1) && bid == 0 && tid == 0) {
        const float2* A2 = (const float2*)A4;
        float2 a = A2[N - 1];
        atomicAdd(&g_hist[0][fkey(bg ? a.y : a.x) >> SHIFT], 1u);
        atomicAdd(&g_hist[1][fkey(bg ? a.x : a.y) >> SHIFT], 1u);
    }
    grid_sync();

    // ---- P2: chunk sums from g_hist + offset tables + worklist (blocks<NCHUNK) -
    if (bid < NCHUNK) {
        #pragma unroll
        for (int hh = 0; hh < 2; hh++) {
            // 1) each thread scalar-sums BPT=32 consecutive bins (uint4 loads)
            {
                const uint4* h4 = (const uint4*)g_hist[hh];
                unsigned sum = 0;
                #pragma unroll
                for (int q = 0; q < BPT / 4; q++) {
                    uint4 c = h4[tid * (BPT / 4) + q];
                    sum += c.x + c.y + c.z + c.w;
                }
                s_u32[tid] = sum;
            }
            __syncthreads();
            // 2) chunk sums: chunk c = s_u32[4c]+..+s_u32[4c+3] -> s_u32[512+c]
            if (tid < NCHUNK)
                s_u32[512 + tid] = s_u32[4 * tid] + s_u32[4 * tid + 1] +
                                   s_u32[4 * tid + 2] + s_u32[4 * tid + 3];
            __syncthreads();
            // 3) inclusive scan over 128 chunk sums
            for (int off = 1; off < NCHUNK; off <<= 1) {
                unsigned w = (tid < NCHUNK && tid >= off) ? s_u32[512 + tid - off] : 0u;
                __syncthreads();
                if (tid < NCHUNK) s_u32[512 + tid] += w;
                __syncthreads();
            }
            const unsigned total = s_u32[512 + NCHUNK - 1];
            unsigned my_csum = 0;
            if (tid < NCHUNK) my_csum = s_u32[512 + tid];
            const unsigned incl_bid = s_u32[512 + bid];
            __syncthreads();
            (void)my_csum;

            // exclusive offset of my chunk = inclusive[bid] - chunksum[bid]
            unsigned csum_bid;
            {
                // recompute chunk bid's sum cheaply from the partials layout:
                // partials were overwritten? No: s_u32[0..512) still holds the
                // per-thread partials for THIS hh. chunk bid = partials[4*bid..+3].
                csum_bid = s_u32[4 * bid] + s_u32[4 * bid + 1] +
                           s_u32[4 * bid + 2] + s_u32[4 * bid + 3];
            }
            const unsigned choff = incl_bid - csum_bid;

            // 4) scan my chunk's CH=128 bins (slots [1024,1152) to keep partials)
            unsigned cnt = 0;
            if (tid < CH) { cnt = g_hist[hh][bid * CH + tid]; s_u32[1024 + tid] = cnt; }
            __syncthreads();
            for (int off = 1; off < CH; off <<= 1) {
                unsigned w = (tid < CH && tid >= off) ? s_u32[1024 + tid - off] : 0u;
                __syncthreads();
                if (tid < CH) s_u32[1024 + tid] += w;
                __syncthreads();
            }
            if (tid < CH) {
                const int b = bid * CH + tid;
                const unsigned incl = s_u32[1024 + tid] + choff;
                // top-K (sel0 from hist0, sel2 from hist1)
                const int selt = hh ? 2 : 0;
                const unsigned above = total - incl;
                g_base[selt][b] = (int)above;
                if (above < uK && cnt > 0) {
                    if (above + cnt >= uK) g_bin[selt] = (unsigned)b;
                    for (int sub = 0; sub * SUB < (int)cnt; sub++) {
                        int w = atomicAdd(&g_nwork, 1);
                        if (w < WLCAP)
                            g_work[w] = make_int4(selt | (sub << 2), b, (int)above, (int)cnt);
                    }
                }
                // bottom-K (hist0 -> sel1)
                if (hh == 0) {
                    const unsigned below = incl - cnt;
                    g_base[1][b] = (int)below;
                    if (below < uK && cnt > 0) {
                        if (below + cnt >= uK) g_bin[1] = (unsigned)b;
                        for (int sub = 0; sub * SUB < (int)cnt; sub++) {
                            int w = atomicAdd(&g_nwork, 1);
                            if (w < WLCAP)
                                g_work[w] = make_int4(1 | (sub << 2), b, (int)below, (int)cnt);
                        }
                    }
                }
            }
            __syncthreads();
        }
    }
    grid_sync();

    // ---- P3: compact/scatter from REGISTERS ------------------------------------
    {
        const unsigned lo0 = g_bin[0], hi1 = g_bin[1], lo2 = g_bin[2];
        for (int i = i0; i < N2; i += gsz) {
            float4 a = (i == i0) ? areg : A4[i];
            #pragma unroll
            for (int e = 0; e < 2; e++) {
                float v  = e ? (bg ? a.w : a.z) : (bg ? a.y : a.x);
                float vo = e ? (bg ? a.z : a.w) : (bg ? a.x : a.y);
                const int idx = i * 2 + e;
                unsigned k0 = fkey(v), k2 = fkey(vo);
                unsigned b0 = k0 >> SHIFT, b2 = k2 >> SHIFT;
                unsigned long long il = (unsigned)(~(unsigned)idx);
                if (b0 >= lo0) {
                    int p = atomicAdd(&g_base[0][b0], 1);
                    if (p < CAP) g_scat[0][p] = ((unsigned long long)k0 << 32) | il;
                }
                if (b0 <= hi1) {
                    int p = atomicAdd(&g_base[1][b0], 1);
                    if (p < CAP) g_scat[1][p] = ((unsigned long long)(~k0) << 32) | il;
                }
                if (b2 >= lo2) {
                    int p = atomicAdd(&g_base[2][b2], 1);
                    if (p < CAP) g_scat[2][p] = ((unsigned long long)k2 << 32) | il;
                }
            }
        }
        if ((N & 1) && bid == 0 && tid == 0) {
            const float2* A2 = (const float2*)A4;
            float2 a = A2[N - 1];
            float v = bg ? a.y : a.x, vo = bg ? a.x : a.y;
            unsigned k0 = fkey(v), k2 = fkey(vo);
            unsigned b0 = k0 >> SHIFT, b2 = k2 >> SHIFT;
            unsigned long long il = (unsigned)(~(unsigned)(N - 1));
            if (b0 >= lo0) {
                int p = atomicAdd(&g_base[0][b0], 1);
                if (p < CAP) g_scat[0][p] = ((unsigned long long)k0 << 32) | il;
            }
            if (b0 <= hi1) {
                int p = atomicAdd(&g_base[1][b0], 1);
                if (p < CAP) g_scat[1][p] = ((unsigned long long)(~k0) << 32) | il;
            }
            if (b2 >= lo2) {
                int p = atomicAdd(&g_base[2][b2], 1);
                if (p < CAP) g_scat[2][p] = ((unsigned long long)k2 << 32) | il;
            }
        }
    }
    grid_sync();

    // ---- P4: rank worklist entries; zero g_hist (dead after P2) ----------------
    {
        const int nwork = g_nwork < WLCAP ? g_nwork : WLCAP;
        for (int e = bid; e < nwork; e += BLKS) {
            int4 w = g_work[e];
            const int sel = w.x & 3, sub = w.x >> 2;
            const int start = w.z;
            int cnt = w.w;
            if (start + cnt > CAP) cnt = CAP - start;
            if (cnt > SEGB) cnt = SEGB;
            const int lo = sub * SUB;
            int hi = lo + SUB; if (hi > cnt) hi = cnt;
            if (lo >= cnt) continue;
            const unsigned long long* seg = &g_scat[sel][start];

            if (cnt == 1) {
                if (tid == 0 && start < K)
                    g_idx[sel * K + start] = (int)(~(unsigned)(seg[0] & 0xFFFFFFFFull));
                continue;
            }
            for (int j = tid; j < cnt; j += THR) s_u64[j] = seg[j];
            __syncthreads();
            for (int i = lo + tid; i < hi; i += THR) {
                unsigned long long key = s_u64[i];
                int rank = 0;
                int j = 0;
                #pragma unroll 4
                for (; j + 3 < cnt; j += 4) {
                    rank += (s_u64[j]     > key);
                    rank += (s_u64[j + 1] > key);
                    rank += (s_u64[j + 2] > key);
                    rank += (s_u64[j + 3] > key);
                }
                for (; j < cnt; j++) rank += (s_u64[j] > key);
                int pos = start + rank;
                if (pos < K)
                    g_idx[sel * K + pos] = (int)(~(unsigned)(key & 0xFFFFFFFFull));
            }
            __syncthreads();
        }
        // zero histograms for the next graph replay
        uint4* hp = (uint4*)g_hist;
        const int totalw = 2 * NBINS / 4;
        for (int i = bid * THR + tid; i < totalw; i += gsz)
            hp[i] = make_uint4(0u, 0u, 0u, 0u);
    }
    grid_sync();

    // ---- P5: gemv/softmax (2 rows per warp); reset g_nwork ----------------------
    {
        if (bid == 0 && tid == 0) g_nwork = 0;

        float* ws0 = s_f;            // [0,D): W[:,0]
        float* ws1 = s_f + D;        // [D,2D): W[:,1]
        for (int j = tid; j < D; j += THR) {
            ws0[j] = W[j * 2 + 0];
            ws1[j] = W[j * 2 + 1];
        }
        __syncthreads();
        const float4* w04 = (const float4*)ws0;
        const float4* w14 = (const float4*)ws1;

        const int warp = tid >> 5, lane = tid & 31;
        const int nwarps = BLKS * (THR >> 5);
        const int wgid = bid * (THR >> 5) + warp;
        const int total = 3 * K;
        const int nq = D >> 2;
        const float bb0 = bvec[0], bb1 = bvec[1];

        for (int rbase = wgid * 2; rbase < total; rbase += nwarps * 2) {
            const bool two = (rbase + 1 < total);
            const int ia = g_idx[rbase];
            const int ib = two ? g_idx[rbase + 1] : ia;
            const float4* pa = (const float4*)(h + (size_t)ia * D);
            const float4* pb = (const float4*)(h + (size_t)ib * D);

            float a0 = 0.f, a1 = 0.f, b0 = 0.f, b1 = 0.f;
            int t = lane;
            for (; t + 96 < nq; t += 128) {
                float4 va0 = pa[t];
                float4 va1 = pa[t + 32];
                float4 va2 = pa[t + 64];
                float4 va3 = pa[t + 96];
                float4 vb0 = pb[t];
                float4 vb1 = pb[t + 32];
                float4 vb2 = pb[t + 64];
                float4 vb3 = pb[t + 96];
                #pragma unroll
                for (int u = 0; u < 4; u++) {
                    float4 va = (u == 0) ? va0 : (u == 1) ? va1 : (u == 2) ? va2 : va3;
                    float4 vb = (u == 0) ? vb0 : (u == 1) ? vb1 : (u == 2) ? vb2 : vb3;
                    float4 w0 = w04[t + u * 32];
                    float4 w1 = w14[t + u * 32];
                    a0 = fmaf(va.x, w0.x, a0);  a1 = fmaf(va.x, w1.x, a1);
                    b0 = fmaf(vb.x, w0.x, b0);  b1 = fmaf(vb.x, w1.x, b1);
                    a0 = fmaf(va.y, w0.y, a0);  a1 = fmaf(va.y, w1.y, a1);
                    b0 = fmaf(vb.y, w0.y, b0);  b1 = fmaf(vb.y, w1.y, b1);
                    a0 = fmaf(va.z, w0.z, a0);  a1 = fmaf(va.z, w1.z, a1);
                    b0 = fmaf(vb.z, w0.z, b0);  b1 = fmaf(vb.z, w1.z, b1);
                    a0 = fmaf(va.w, w0.w, a0);  a1 = fmaf(va.w, w1.w, a1);
                    b0 = fmaf(vb.w, w0.w, b0);  b1 = fmaf(vb.w, w1.w, b1);
                }
            }
            for (; t < nq; t += 32) {
                float4 va = pa[t];
                float4 vb = pb[t];
                float4 w0 = w04[t];
                float4 w1 = w14[t];
                a0 = fmaf(va.x, w0.x, a0);  a1 = fmaf(va.x, w1.x, a1);
                b0 = fmaf(vb.x, w0.x, b0);  b1 = fmaf(vb.x, w1.x, b1);
                a0 = fmaf(va.y, w0.y, a0);  a1 = fmaf(va.y, w1.y, a1);
                b0 = fmaf(vb.y, w0.y, b0);  b1 = fmaf(vb.y, w1.y, b1);
                a0 = fmaf(va.z, w0.z, a0);  a1 = fmaf(va.z, w1.z, a1);
                b0 = fmaf(vb.z, w0.z, b0);  b1 = fmaf(vb.z, w1.z, b1);
                a0 = fmaf(va.w, w0.w, a0);  a1 = fmaf(va.w, w1.w, a1);
                b0 = fmaf(vb.w, w0.w, b0);  b1 = fmaf(vb.w, w1.w, b1);
            }
            #pragma unroll
            for (int o = 16; o; o >>= 1) {
                a0 += __shfl_down_sync(0xFFFFFFFFu, a0, o);
                a1 += __shfl_down_sync(0xFFFFFFFFu, a1, o);
                b0 += __shfl_down_sync(0xFFFFFFFFu, b0, o);
                b1 += __shfl_down_sync(0xFFFFFFFFu, b1, o);
            }
            if (lane == 0) {
                {
                    int r = rbase;
                    float z0 = a0 + bb0, z1 = a1 + bb1;
                    float m = fmaxf(z0, z1);
                    float e0 = expf(z0 - m), e1 = expf(z1 - m);
                    float inv = 1.0f / (e0 + e1);
                    out[r] = (r < K) ? 1.0f : 0.0f;
                    out[3 * K + r * 2 + 0] = z0;
                    out[3 * K + r * 2 + 1] = z1;
                    out[9 * K + r * 2 + 0] = e0 * inv;
                    out[9 * K + r * 2 + 1] = e1 * inv;
                }
                if (two) {
                    int r = rbase + 1;
                    float z0 = b0 + bb0, z1 = b1 + bb1;
                    float m = fmaxf(z0, z1);
                    float e0 = expf(z0 - m), e1 = expf(z1 - m);
                    float inv = 1.0f / (e0 + e1);
                    out[r] = (r < K) ? 1.0f : 0.0f;
                    out[3 * K + r * 2 + 0] = z0;
                    out[3 * K + r * 2 + 1] = z1;
                    out[9 * K + r * 2 + 0] = e0 * inv;
                    out[9 * K + r * 2 + 1] = e1 * inv;
                }
            }
        }
    }
}

extern "C" void kernel_launch(void* const* d_in, const int* in_sizes, int n_in,
                              void* d_out, int out_size) {
    const float* h = (const float*)d_in[0];   // (N,1,D)
    const float* A = (const float*)d_in[1];   // (N,1,2)
    const float* W = (const float*)d_in[2];   // (D,2)
    const float* b = (const float*)d_in[3];   // (2,)
    const int* bag = (const int*)d_in[4];

    const int N = in_sizes[1] / 2;
    const int D = in_sizes[0] / N;
    int K = (int)(0.02 * (double)N);
    if (K == 0) K = 8;
    if (K > KMAX) K = KMAX;

    fused_kernel<<<BLKS, THR>>>(h, (const float4*)A, W, b, bag,
                                (float*)d_out, N, D, K);
}

// round 16
// speedup vs baseline: 2.2910x; 1.0340x over previous
#include <cuda_runtime.h>
#include <cuda_bf16.h>
#include <math.h>

// ---------------------------------------------------------------------------
// SINGLE-KERNEL fused pipeline (persistent grid + device grid barriers).
// 3x exact top-K over columns of A (N x 2), (value desc, index asc) = lax.top_k.
// 296 blocks x 256 threads; 4 grid barriers, ONE pass over A:
//   P1 hist    : 16384-bin global histograms of fkey(v), fkey(vo); A in regs
//   P2 base    : 128 blocks; warp-shuffle scans (few syncthreads): chunk sums
//                from g_hist, chunk scan (warp 0), 128-bin scan (4 warps);
//                writes g_base, thresholds, worklist (fat bins SUB-split)
//   P3 compact : scatter candidates (A values from REGISTERS) via atomicAdd
//   P4 rank    : one block per worklist entry, rank-by-comparison; also zeroes
//                g_hist for the next replay
//   P5 gemv    : 4 rows/warp single-trip gather + 512->2 GEMV (smem W) + softmax
// State zero at module load; each call re-zeroes => every call identical.
// Output (float32, 15K): [0,3K) labels | [3K,9K) logits | [9K,15K) softmax
// ---------------------------------------------------------------------------

#define NBINS   16384
#define SHIFT   18
#define NCHUNK  128
#define CH      128                // bins per chunk
#define SUB     128                // keys ranked per worklist entry
#define CAP     4096
#define KMAX    2048
#define SEGB    1024
#define WLCAP   8192
#define BLKS    296
#define THR     256

__device__ unsigned            g_hist[2][NBINS];
__device__ int                 g_base[3][NBINS];
__device__ unsigned            g_bin[3];            // lo0 (>=), hi1 (<=), lo2 (>=)
__device__ int                 g_nwork;
__device__ int4                g_work[WLCAP];       // {sel|sub<<2, bin, start, cnt}
__device__ unsigned long long  g_scat[3][CAP];
__device__ int                 g_idx[3 * KMAX];
__device__ unsigned            g_arrive;
__device__ volatile unsigned   g_gen;

__device__ __forceinline__ unsigned fkey(float f) {
    unsigned u = __float_as_uint(f);
    return (u & 0x80000000u) ? ~u : (u | 0x80000000u);   // monotonic
}

// Generation-counter grid barrier. Safe: 296 blocks, >=304 resident slots
// at __launch_bounds__(256, 2) on 152 SMs.
__device__ __forceinline__ void grid_sync() {
    __syncthreads();
    if (threadIdx.x == 0) {
        unsigned gen = g_gen;
        __threadfence();                               // release
        if (atomicAdd(&g_arrive, 1u) == (unsigned)BLKS - 1u) {
            g_arrive = 0u;
            __threadfence();
            g_gen = gen + 1u;
        } else {
            while (g_gen == gen) __nanosleep(32);
            __threadfence();                           // acquire
        }
    }
    __syncthreads();
}

__global__ __launch_bounds__(THR, 2)
void fused_kernel(const float* __restrict__ h, const float4* __restrict__ A4,
                  const float* __restrict__ W, const float* __restrict__ bvec,
                  const int* __restrict__ bag, float* __restrict__ out,
                  int N, int D, int K) {
    __shared__ unsigned long long s_u64[SEGB];        // 8KB = 2048 u32, aliased
    unsigned* s_u32 = (unsigned*)s_u64;
    float*    s_f   = (float*)s_u64;

    const int tid = threadIdx.x;
    const int bid = blockIdx.x;
    const int bg  = __ldg(bag);
    const unsigned uK = (unsigned)K;
    const int N2 = N >> 1;
    const int gsz = BLKS * THR;
    const int i0 = bid * THR + tid;

    // ---- P1: histograms; keep this thread's float4 in registers ---------------
    float4 areg = make_float4(0.f, 0.f, 0.f, 0.f);
    if (i0 < N2) areg = A4[i0];
    for (int i = i0; i < N2; i += gsz) {
        float4 a = (i == i0) ? areg : A4[i];
        float v0  = bg ? a.y : a.x,  vo0 = bg ? a.x : a.y;
        float v1  = bg ? a.w : a.z,  vo1 = bg ? a.z : a.w;
        atomicAdd(&g_hist[0][fkey(v0)  >> SHIFT], 1u);
        atomicAdd(&g_hist[1][fkey(vo0) >> SHIFT], 1u);
        atomicAdd(&g_hist[0][fkey(v1)  >> SHIFT], 1u);
        atomicAdd(&g_hist[1][fkey(vo1) >> SHIFT], 1u);
    }
    if ((N & 1) && bid == 0 && tid == 0) {
        const float2* A2 = (const float2*)A4;
        float2 a = A2[N - 1];
        atomicAdd(&g_hist[0][fkey(bg ? a.y : a.x) >> SHIFT], 1u);
        atomicAdd(&g_hist[1][fkey(bg ? a.x : a.y) >> SHIFT], 1u);
    }
    grid_sync();

    // ---- P2: shuffle-scan offset tables + worklist (blocks < NCHUNK) -----------
    if (bid < NCHUNK) {
        const int lane = tid & 31;
        #pragma unroll
        for (int hh = 0; hh < 2; hh++) {
            // 1) per-thread partial: sum 64 consecutive bins (16 uint4 loads)
            {
                const uint4* h4 = (const uint4*)g_hist[hh];
                unsigned sum = 0;
                #pragma unroll
                for (int q = 0; q < 16; q++) {
                    uint4 c = h4[tid * 16 + q];
                    sum += c.x + c.y + c.z + c.w;
                }
                s_u32[tid] = sum;       // partials: thread t = bins [64t,64t+64)
            }
            __syncthreads();
            // 2) warp 0: chunk sums (4 chunks/lane) + inclusive shuffle scan
            if (tid < 32) {
                unsigned c0 = s_u32[8 * tid + 0] + s_u32[8 * tid + 1];
                unsigned c1 = s_u32[8 * tid + 2] + s_u32[8 * tid + 3];
                unsigned c2 = s_u32[8 * tid + 4] + s_u32[8 * tid + 5];
                unsigned c3 = s_u32[8 * tid + 6] + s_u32[8 * tid + 7];
                unsigned p0 = c0, p1 = p0 + c1, p2 = p1 + c2, p3 = p2 + c3;
                unsigned inc = p3;
                #pragma unroll
                for (int o = 1; o < 32; o <<= 1) {
                    unsigned v = __shfl_up_sync(0xFFFFFFFFu, inc, o);
                    if (tid >= o) inc += v;
                }
                unsigned excl = inc - p3;
                s_u32[256 + 4 * tid + 0] = p0 + excl;
                s_u32[256 + 4 * tid + 1] = p1 + excl;
                s_u32[256 + 4 * tid + 2] = p2 + excl;
                s_u32[256 + 4 * tid + 3] = p3 + excl;
            }
            __syncthreads();
            const unsigned total = s_u32[256 + NCHUNK - 1];
            const unsigned csum_bid = s_u32[2 * bid] + s_u32[2 * bid + 1];
            const unsigned choff = s_u32[256 + bid] - csum_bid;

            // 3) bin scan: threads<128 (warps 0-3), shuffle scan + warp offsets
            unsigned cnt = 0, incl = 0;
            if (tid < CH) {
                cnt = g_hist[hh][bid * CH + tid];
                unsigned v = cnt;
                #pragma unroll
                for (int o = 1; o < 32; o <<= 1) {
                    unsigned w = __shfl_up_sync(0xFFFFFFFFu, v, o);
                    if (lane >= o) v += w;
                }
                if (lane == 31) s_u32[384 + (tid >> 5)] = v;  // 4 warp totals
                incl = v;
            }
            __syncthreads();
            if (tid < CH) {
                unsigned woff = 0;
                #pragma unroll
                for (int w = 0; w < 3; w++)
                    if (w < (tid >> 5)) woff += s_u32[384 + w];
                incl += woff + choff;

                const int b = bid * CH + tid;
                // top-K (sel0 from hist0, sel2 from hist1)
                const int selt = hh ? 2 : 0;
                const unsigned above = total - incl;
                g_base[selt][b] = (int)above;
                if (above < uK && cnt > 0) {
                    if (above + cnt >= uK) g_bin[selt] = (unsigned)b;
                    for (int sub = 0; sub * SUB < (int)cnt; sub++) {
                        int w = atomicAdd(&g_nwork, 1);
                        if (w < WLCAP)
                            g_work[w] = make_int4(selt | (sub << 2), b, (int)above, (int)cnt);
                    }
                }
                // bottom-K (hist0 -> sel1)
                if (hh == 0) {
                    const unsigned below = incl - cnt;
                    g_base[1][b] = (int)below;
                    if (below < uK && cnt > 0) {
                        if (below + cnt >= uK) g_bin[1] = (unsigned)b;
                        for (int sub = 0; sub * SUB < (int)cnt; sub++) {
                            int w = atomicAdd(&g_nwork, 1);
                            if (w < WLCAP)
                                g_work[w] = make_int4(1 | (sub << 2), b, (int)below, (int)cnt);
                        }
                    }
                }
            }
            __syncthreads();
        }
    }
    grid_sync();

    // ---- P3: compact/scatter from REGISTERS ------------------------------------
    {
        const unsigned lo0 = g_bin[0], hi1 = g_bin[1], lo2 = g_bin[2];
        for (int i = i0; i < N2; i += gsz) {
            float4 a = (i == i0) ? areg : A4[i];
            #pragma unroll
            for (int e = 0; e < 2; e++) {
                float v  = e ? (bg ? a.w : a.z) : (bg ? a.y : a.x);
                float vo = e ? (bg ? a.z : a.w) : (bg ? a.x : a.y);
                const int idx = i * 2 + e;
                unsigned k0 = fkey(v), k2 = fkey(vo);
                unsigned b0 = k0 >> SHIFT, b2 = k2 >> SHIFT;
                unsigned long long il = (unsigned)(~(unsigned)idx);
                if (b0 >= lo0) {
                    int p = atomicAdd(&g_base[0][b0], 1);
                    if (p < CAP) g_scat[0][p] = ((unsigned long long)k0 << 32) | il;
                }
                if (b0 <= hi1) {
                    int p = atomicAdd(&g_base[1][b0], 1);
                    if (p < CAP) g_scat[1][p] = ((unsigned long long)(~k0) << 32) | il;
                }
                if (b2 >= lo2) {
                    int p = atomicAdd(&g_base[2][b2], 1);
                    if (p < CAP) g_scat[2][p] = ((unsigned long long)k2 << 32) | il;
                }
            }
        }
        if ((N & 1) && bid == 0 && tid == 0) {
            const float2* A2 = (const float2*)A4;
            float2 a = A2[N - 1];
            float v = bg ? a.y : a.x, vo = bg ? a.x : a.y;
            unsigned k0 = fkey(v), k2 = fkey(vo);
            unsigned b0 = k0 >> SHIFT, b2 = k2 >> SHIFT;
            unsigned long long il = (unsigned)(~(unsigned)(N - 1));
            if (b0 >= lo0) {
                int p = atomicAdd(&g_base[0][b0], 1);
                if (p < CAP) g_scat[0][p] = ((unsigned long long)k0 << 32) | il;
            }
            if (b0 <= hi1) {
                int p = atomicAdd(&g_base[1][b0], 1);
                if (p < CAP) g_scat[1][p] = ((unsigned long long)(~k0) << 32) | il;
            }
            if (b2 >= lo2) {
                int p = atomicAdd(&g_base[2][b2], 1);
                if (p < CAP) g_scat[2][p] = ((unsigned long long)k2 << 32) | il;
            }
        }
    }
    grid_sync();

    // ---- P4: rank worklist entries; zero g_hist (dead after P2) ----------------
    {
        const int nwork = g_nwork < WLCAP ? g_nwork : WLCAP;
        for (int e = bid; e < nwork; e += BLKS) {
            int4 w = g_work[e];
            const int sel = w.x & 3, sub = w.x >> 2;
            const int start = w.z;
            int cnt = w.w;
            if (start + cnt > CAP) cnt = CAP - start;
            if (cnt > SEGB) cnt = SEGB;
            const int lo = sub * SUB;
            int hi = lo + SUB; if (hi > cnt) hi = cnt;
            if (lo >= cnt) continue;
            const unsigned long long* seg = &g_scat[sel][start];

            if (cnt == 1) {
                if (tid == 0 && start < K)
                    g_idx[sel * K + start] = (int)(~(unsigned)(seg[0] & 0xFFFFFFFFull));
                continue;
            }
            for (int j = tid; j < cnt; j += THR) s_u64[j] = seg[j];
            __syncthreads();
            for (int i = lo + tid; i < hi; i += THR) {
                unsigned long long key = s_u64[i];
                int rank = 0;
                int j = 0;
                #pragma unroll 4
                for (; j + 3 < cnt; j += 4) {
                    rank += (s_u64[j]     > key);
                    rank += (s_u64[j + 1] > key);
                    rank += (s_u64[j + 2] > key);
                    rank += (s_u64[j + 3] > key);
                }
                for (; j < cnt; j++) rank += (s_u64[j] > key);
                int pos = start + rank;
                if (pos < K)
                    g_idx[sel * K + pos] = (int)(~(unsigned)(key & 0xFFFFFFFFull));
            }
            __syncthreads();
        }
        // zero histograms for the next graph replay
        uint4* hp = (uint4*)g_hist;
        const int totalw = 2 * NBINS / 4;
        for (int i = bid * THR + tid; i < totalw; i += gsz)
            hp[i] = make_uint4(0u, 0u, 0u, 0u);
    }
    grid_sync();

    // ---- P5: gemv/softmax (4 rows/warp, single trip); reset g_nwork -------------
    {
        if (bid == 0 && tid == 0) g_nwork = 0;

        float* ws0 = s_f;            // [0,D): W[:,0]
        float* ws1 = s_f + D;        // [D,2D): W[:,1]
        for (int j = tid; j < D; j += THR) {
            ws0[j] = W[j * 2 + 0];
            ws1[j] = W[j * 2 + 1];
        }
        __syncthreads();
        const float4* w04 = (const float4*)ws0;
        const float4* w14 = (const float4*)ws1;

        const int warp = tid >> 5, lane = tid & 31;
        const int nwarps = BLKS * (THR >> 5);
        const int wgid = bid * (THR >> 5) + warp;
        const int total = 3 * K;
        const int nq = D >> 2;
        const float bb0 = bvec[0], bb1 = bvec[1];

        for (int rbase = wgid * 4; rbase < total; rbase += nwarps * 4) {
            const int i0r = g_idx[rbase];
            const int i1r = (rbase + 1 < total) ? g_idx[rbase + 1] : i0r;
            const int i2r = (rbase + 2 < total) ? g_idx[rbase + 2] : i0r;
            const int i3r = (rbase + 3 < total) ? g_idx[rbase + 3] : i0r;
            const float4* p0 = (const float4*)(h + (size_t)i0r * D);
            const float4* p1 = (const float4*)(h + (size_t)i1r * D);
            const float4* p2 = (const float4*)(h + (size_t)i2r * D);
            const float4* p3 = (const float4*)(h + (size_t)i3r * D);

            float c00 = 0.f, c01 = 0.f, c10 = 0.f, c11 = 0.f;
            float c20 = 0.f, c21 = 0.f, c30 = 0.f, c31 = 0.f;

            int t = lane;
            for (; t + 32 < nq; t += 64) {
                float4 a0 = p0[t],      a1 = p1[t],      a2 = p2[t],      a3 = p3[t];
                float4 d0 = p0[t + 32], d1 = p1[t + 32], d2 = p2[t + 32], d3 = p3[t + 32];
                float4 w0 = w04[t],      w1 = w14[t];
                float4 e0 = w04[t + 32], e1 = w14[t + 32];
                c00 = fmaf(a0.x, w0.x, c00); c01 = fmaf(a0.x, w1.x, c01);
                c10 = fmaf(a1.x, w0.x, c10); c11 = fmaf(a1.x, w1.x, c11);
                c20 = fmaf(a2.x, w0.x, c20); c21 = fmaf(a2.x, w1.x, c21);
                c30 = fmaf(a3.x, w0.x, c30); c31 = fmaf(a3.x, w1.x, c31);
                c00 = fmaf(a0.y, w0.y, c00); c01 = fmaf(a0.y, w1.y, c01);
                c10 = fmaf(a1.y, w0.y, c10); c11 = fmaf(a1.y, w1.y, c11);
                c20 = fmaf(a2.y, w0.y, c20); c21 = fmaf(a2.y, w1.y, c21);
                c30 = fmaf(a3.y, w0.y, c30); c31 = fmaf(a3.y, w1.y, c31);
                c00 = fmaf(a0.z, w0.z, c00); c01 = fmaf(a0.z, w1.z, c01);
                c10 = fmaf(a1.z, w0.z, c10); c11 = fmaf(a1.z, w1.z, c11);
                c20 = fmaf(a2.z, w0.z, c20); c21 = fmaf(a2.z, w1.z, c21);
                c30 = fmaf(a3.z, w0.z, c30); c31 = fmaf(a3.z, w1.z, c31);
                c00 = fmaf(a0.w, w0.w, c00); c01 = fmaf(a0.w, w1.w, c01);
                c10 = fmaf(a1.w, w0.w, c10); c11 = fmaf(a1.w, w1.w, c11);
                c20 = fmaf(a2.w, w0.w, c20); c21 = fmaf(a2.w, w1.w, c21);
                c30 = fmaf(a3.w, w0.w, c30); c31 = fmaf(a3.w, w1.w, c31);
                c00 = fmaf(d0.x, e0.x, c00); c01 = fmaf(d0.x, e1.x, c01);
                c10 = fmaf(d1.x, e0.x, c10); c11 = fmaf(d1.x, e1.x, c11);
                c20 = fmaf(d2.x, e0.x, c20); c21 = fmaf(d2.x, e1.x, c21);
                c30 = fmaf(d3.x, e0.x, c30); c31 = fmaf(d3.x, e1.x, c31);
                c00 = fmaf(d0.y, e0.y, c00); c01 = fmaf(d0.y, e1.y, c01);
                c10 = fmaf(d1.y, e0.y, c10); c11 = fmaf(d1.y, e1.y, c11);
                c20 = fmaf(d2.y, e0.y, c20); c21 = fmaf(d2.y, e1.y, c21);
                c30 = fmaf(d3.y, e0.y, c30); c31 = fmaf(d3.y, e1.y, c31);
                c00 = fmaf(d0.z, e0.z, c00); c01 = fmaf(d0.z, e1.z, c01);
                c10 = fmaf(d1.z, e0.z, c10); c11 = fmaf(d1.z, e1.z, c11);
                c20 = fmaf(d2.z, e0.z, c20); c21 = fmaf(d2.z, e1.z, c21);
                c30 = fmaf(d3.z, e0.z, c30); c31 = fmaf(d3.z, e1.z, c31);
                c00 = fmaf(d0.w, e0.w, c00); c01 = fmaf(d0.w, e1.w, c01);
                c10 = fmaf(d1.w, e0.w, c10); c11 = fmaf(d1.w, e1.w, c11);
                c20 = fmaf(d2.w, e0.w, c20); c21 = fmaf(d2.w, e1.w, c21);
                c30 = fmaf(d3.w, e0.w, c30); c31 = fmaf(d3.w, e1.w, c31);
            }
            for (; t < nq; t += 32) {
                float4 a0 = p0[t], a1 = p1[t], a2 = p2[t], a3 = p3[t];
                float4 w0 = w04[t], w1 = w14[t];
                c00 = fmaf(a0.x, w0.x, c00); c01 = fmaf(a0.x, w1.x, c01);
                c10 = fmaf(a1.x, w0.x, c10); c11 = fmaf(a1.x, w1.x, c11);
                c20 = fmaf(a2.x, w0.x, c20); c21 = fmaf(a2.x, w1.x, c21);
                c30 = fmaf(a3.x, w0.x, c30); c31 = fmaf(a3.x, w1.x, c31);
                c00 = fmaf(a0.y, w0.y, c00); c01 = fmaf(a0.y, w1.y, c01);
                c10 = fmaf(a1.y, w0.y, c10); c11 = fmaf(a1.y, w1.y, c11);
                c20 = fmaf(a2.y, w0.y, c20); c21 = fmaf(a2.y, w1.y, c21);
                c30 = fmaf(a3.y, w0.y, c30); c31 = fmaf(a3.y, w1.y, c31);
                c00 = fmaf(a0.z, w0.z, c00); c01 = fmaf(a0.z, w1.z, c01);
                c10 = fmaf(a1.z, w0.z, c10); c11 = fmaf(a1.z, w1.z, c11);
                c20 = fmaf(a2.z, w0.z, c20); c21 = fmaf(a2.z, w1.z, c21);
                c30 = fmaf(a3.z, w0.z, c30); c31 = fmaf(a3.z, w1.z, c31);
                c00 = fmaf(a0.w, w0.w, c00); c01 = fmaf(a0.w, w1.w, c01);
                c10 = fmaf(a1.w, w0.w, c10); c11 = fmaf(a1.w, w1.w, c11);
                c20 = fmaf(a2.w, w0.w, c20); c21 = fmaf(a2.w, w1.w, c21);
                c30 = fmaf(a3.w, w0.w, c30); c31 = fmaf(a3.w, w1.w, c31);
            }

            #pragma unroll
            for (int o = 16; o; o >>= 1) {
                c00 += __shfl_down_sync(0xFFFFFFFFu, c00, o);
                c01 += __shfl_down_sync(0xFFFFFFFFu, c01, o);
                c10 += __shfl_down_sync(0xFFFFFFFFu, c10, o);
                c11 += __shfl_down_sync(0xFFFFFFFFu, c11, o);
                c20 += __shfl_down_sync(0xFFFFFFFFu, c20, o);
                c21 += __shfl_down_sync(0xFFFFFFFFu, c21, o);
                c30 += __shfl_down_sync(0xFFFFFFFFu, c30, o);
                c31 += __shfl_down_sync(0xFFFFFFFFu, c31, o);
            }

            if (lane == 0) {
                float z0s[4] = {c00, c10, c20, c30};
                float z1s[4] = {c01, c11, c21, c31};
                #pragma unroll
                for (int q = 0; q < 4; q++) {
                    int r = rbase + q;
                    if (r >= total) break;
                    float z0 = z0s[q] + bb0, z1 = z1s[q] + bb1;
                    float m = fmaxf(z0, z1);
                    float e0 = expf(z0 - m), e1 = expf(z1 - m);
                    float inv = 1.0f / (e0 + e1);
                    out[r] = (r < K) ? 1.0f : 0.0f;
                    out[3 * K + r * 2 + 0] = z0;
                    out[3 * K + r * 2 + 1] = z1;
                    out[9 * K + r * 2 + 0] = e0 * inv;
                    out[9 * K + r * 2 + 1] = e1 * inv;
                }
            }
        }
    }
}

extern "C" void kernel_launch(void* const* d_in, const int* in_sizes, int n_in,
                              void* d_out, int out_size) {
    const float* h = (const float*)d_in[0];   // (N,1,D)
    const float* A = (const float*)d_in[1];   // (N,1,2)
    const float* W = (const float*)d_in[2];   // (D,2)
    const float* b = (const float*)d_in[3];   // (2,)
    const int* bag = (const int*)d_in[4];

    const int N = in_sizes[1] / 2;
    const int D = in_sizes[0] / N;
    int K = (int)(0.02 * (double)N);
    if (K == 0) K = 8;
    if (K > KMAX) K = KMAX;

    fused_kernel<<<BLKS, THR>>>(h, (const float4*)A, W, b, bag,
                                (float*)d_out, N, D, K);
}